// round 2
// baseline (speedup 1.0000x reference)
#include <cuda_runtime.h>
#include <math.h>

// Problem constants
#define BB   2
#define SS   2048
#define EE   1024
#define HH   16
#define DD   64
#define NTOK (BB * SS)   // 4096

// ---------------------------------------------------------------------------
// Scratch (device globals — no allocation allowed in kernel_launch)
// ---------------------------------------------------------------------------
__device__ float g_q[BB * HH * SS * DD];     // [B,H,S,D]
__device__ float g_k[BB * HH * SS * DD];
__device__ float g_v[BB * HH * SS * DD];
__device__ float g_attn[NTOK * EE];          // [B,S,E]

// ---------------------------------------------------------------------------
// Shared GEMM core: C[128x128] tile of A[M,1024] @ W[1024,1024]
// 256 threads, 8x8 per thread, BK=8
// ---------------------------------------------------------------------------
__device__ __forceinline__ void gemm_tile_core(const float* __restrict__ A,
                                               const float* __restrict__ W,
                                               float acc[8][8])
{
    __shared__ float As[8][128];
    __shared__ float Bs[8][128];

    const int tid = threadIdx.x;
    const int tx = tid & 15;        // 0..15 (cols)
    const int ty = tid >> 4;        // 0..15 (rows)
    const int brow = blockIdx.y * 128;
    const int bcol = blockIdx.x * 128;

    // load mapping
    const int arow  = tid >> 1;            // 0..127
    const int acol4 = (tid & 1) * 4;       // 0 or 4
    const int bkrow = tid >> 5;            // 0..7
    const int bcol4 = (tid & 31) * 4;      // 0..124

    const float* Aptr = A + (brow + arow) * EE + acol4;
    const float* Wptr = W + bkrow * EE + bcol + bcol4;

    for (int k0 = 0; k0 < EE; k0 += 8) {
        float4 av = *(const float4*)(Aptr + k0);
        float4 bv = *(const float4*)(Wptr + k0 * EE);

        __syncthreads();   // previous iter done reading smem
        As[acol4 + 0][arow] = av.x;
        As[acol4 + 1][arow] = av.y;
        As[acol4 + 2][arow] = av.z;
        As[acol4 + 3][arow] = av.w;
        *(float4*)&Bs[bkrow][bcol4] = bv;
        __syncthreads();

#pragma unroll
        for (int k = 0; k < 8; k++) {
            float4 a0 = *(const float4*)&As[k][ty * 8];
            float4 a1 = *(const float4*)&As[k][ty * 8 + 4];
            float4 b0 = *(const float4*)&Bs[k][tx * 8];
            float4 b1 = *(const float4*)&Bs[k][tx * 8 + 4];
            float a[8] = {a0.x, a0.y, a0.z, a0.w, a1.x, a1.y, a1.z, a1.w};
            float b[8] = {b0.x, b0.y, b0.z, b0.w, b1.x, b1.y, b1.z, b1.w};
#pragma unroll
            for (int i = 0; i < 8; i++)
#pragma unroll
                for (int j = 0; j < 8; j++)
                    acc[i][j] += a[i] * b[j];
        }
    }
}

// ---------------------------------------------------------------------------
// QKV projection: grid (8, 32, 3); z selects {Q,K,V}. Writes [B,H,S,D].
// ---------------------------------------------------------------------------
__global__ void __launch_bounds__(256)
qkv_kernel(const float* __restrict__ x,
           const float* __restrict__ Wq, const float* __restrict__ bq,
           const float* __restrict__ Wk, const float* __restrict__ bk,
           const float* __restrict__ Wv, const float* __restrict__ bv)
{
    const float* W;
    const float* bias;
    float* dst;
    if (blockIdx.z == 0)      { W = Wq; bias = bq; dst = g_q; }
    else if (blockIdx.z == 1) { W = Wk; bias = bk; dst = g_k; }
    else                      { W = Wv; bias = bv; dst = g_v; }

    float acc[8][8];
#pragma unroll
    for (int i = 0; i < 8; i++)
#pragma unroll
        for (int j = 0; j < 8; j++) acc[i][j] = 0.f;

    gemm_tile_core(x, W, acc);

    const int tid = threadIdx.x;
    const int tx = tid & 15, ty = tid >> 4;
    const int e0 = blockIdx.x * 128 + tx * 8;   // 8-aligned, D=64 -> single head
    const int h  = e0 >> 6;
    const int d0 = e0 & 63;

#pragma unroll
    for (int i = 0; i < 8; i++) {
        int t = blockIdx.y * 128 + ty * 8 + i;  // token
        int b = t >> 11;                        // S = 2048
        int s = t & 2047;
        float* o = dst + ((size_t)(b * HH + h) * SS + s) * DD + d0;
#pragma unroll
        for (int j = 0; j < 8; j++)
            o[j] = acc[i][j] + bias[e0 + j];
    }
}

// ---------------------------------------------------------------------------
// Flash attention, fp32, causal. grid (S/64, B*H), 256 threads.
// Dynamic smem: Qs/Ks/Vs/Ps 64x65 + 3x64 stats.
// ---------------------------------------------------------------------------
#define ATTN_SMEM_FLOATS (4 * 64 * 65 + 3 * 64)

__global__ void __launch_bounds__(256)
attn_kernel()
{
    extern __shared__ float sm[];
    float* Qs    = sm;                 // [64][65]
    float* Ks    = Qs + 64 * 65;
    float* Vs    = Ks + 64 * 65;
    float* Ps    = Vs + 64 * 65;
    float* row_m = Ps + 64 * 65;
    float* row_l = row_m + 64;
    float* row_f = row_l + 64;

    const int tid = threadIdx.x;
    const int tx = tid & 15, ty = tid >> 4;
    const int qt = blockIdx.x;
    const int bh = blockIdx.y;
    const int q0 = qt * 64;

    const float* Qb = g_q + (size_t)bh * SS * DD;
    const float* Kb = g_k + (size_t)bh * SS * DD;
    const float* Vb = g_v + (size_t)bh * SS * DD;

    // load Q tile (pre-scaled by 1/sqrt(D) = 0.125)
    for (int i = tid; i < 64 * 64; i += 256) {
        int r = i >> 6, c = i & 63;
        Qs[r * 65 + c] = Qb[(q0 + r) * DD + c] * 0.125f;
    }
    if (tid < 64) { row_m[tid] = -1e30f; row_l[tid] = 0.f; }

    float acc[4][4];
#pragma unroll
    for (int i = 0; i < 4; i++)
#pragma unroll
        for (int j = 0; j < 4; j++) acc[i][j] = 0.f;

    for (int jt = 0; jt <= qt; jt++) {
        const int k0 = jt * 64;
        __syncthreads();   // previous iteration done with Ks/Vs/Ps (and Q/stats init)
        for (int i = tid; i < 64 * 64; i += 256) {
            int r = i >> 6, c = i & 63;
            Ks[r * 65 + c] = Kb[(k0 + r) * DD + c];
            Vs[r * 65 + c] = Vb[(k0 + r) * DD + c];
        }
        __syncthreads();

        // scores: S = Q @ K^T  (4x4 per thread)
        float s[4][4];
#pragma unroll
        for (int i = 0; i < 4; i++)
#pragma unroll
            for (int j = 0; j < 4; j++) s[i][j] = 0.f;

#pragma unroll 8
        for (int d = 0; d < 64; d++) {
            float a[4], b[4];
#pragma unroll
            for (int i = 0; i < 4; i++) a[i] = Qs[(ty * 4 + i) * 65 + d];
#pragma unroll
            for (int j = 0; j < 4; j++) b[j] = Ks[(tx * 4 + j) * 65 + d];
#pragma unroll
            for (int i = 0; i < 4; i++)
#pragma unroll
                for (int j = 0; j < 4; j++) s[i][j] += a[i] * b[j];
        }

        if (jt == qt) {   // causal mask on diagonal tile (q0 == k0)
#pragma unroll
            for (int i = 0; i < 4; i++)
#pragma unroll
                for (int j = 0; j < 4; j++)
                    if (tx * 4 + j > ty * 4 + i) s[i][j] = -1e30f;
        }

#pragma unroll
        for (int i = 0; i < 4; i++)
#pragma unroll
            for (int j = 0; j < 4; j++)
                Ps[(ty * 4 + i) * 65 + tx * 4 + j] = s[i][j];
        __syncthreads();

        // online softmax: 4 threads per row
        {
            const int row = tid >> 2;
            const int c0  = (tid & 3) * 16;
            float m = -1e30f;
#pragma unroll
            for (int c = 0; c < 16; c++) m = fmaxf(m, Ps[row * 65 + c0 + c]);
            m = fmaxf(m, __shfl_xor_sync(0xffffffffu, m, 1));
            m = fmaxf(m, __shfl_xor_sync(0xffffffffu, m, 2));
            const float mold = row_m[row];
            const float mnew = fmaxf(mold, m);
            float sum = 0.f;
#pragma unroll
            for (int c = 0; c < 16; c++) {
                float p = __expf(Ps[row * 65 + c0 + c] - mnew);
                Ps[row * 65 + c0 + c] = p;
                sum += p;
            }
            sum += __shfl_xor_sync(0xffffffffu, sum, 1);
            sum += __shfl_xor_sync(0xffffffffu, sum, 2);
            if ((tid & 3) == 0) {
                float f = __expf(mold - mnew);
                row_f[row] = f;
                row_l[row] = row_l[row] * f + sum;
                row_m[row] = mnew;
            }
        }
        __syncthreads();

        // rescale + PV
        float f[4];
#pragma unroll
        for (int i = 0; i < 4; i++) f[i] = row_f[ty * 4 + i];
#pragma unroll
        for (int i = 0; i < 4; i++)
#pragma unroll
            for (int j = 0; j < 4; j++) acc[i][j] *= f[i];

#pragma unroll 8
        for (int kv = 0; kv < 64; kv++) {
            float p[4], v[4];
#pragma unroll
            for (int i = 0; i < 4; i++) p[i] = Ps[(ty * 4 + i) * 65 + kv];
#pragma unroll
            for (int j = 0; j < 4; j++) v[j] = Vs[kv * 65 + tx * 4 + j];
#pragma unroll
            for (int i = 0; i < 4; i++)
#pragma unroll
                for (int j = 0; j < 4; j++) acc[i][j] += p[i] * v[j];
        }
    }
    __syncthreads();

    // epilogue: normalize, write [B,S,E] (e = h*64 + d)
    const int b = bh >> 4;   // H = 16
    const int h = bh & 15;
#pragma unroll
    for (int i = 0; i < 4; i++) {
        const int srow = q0 + ty * 4 + i;
        const float inv = 1.f / row_l[ty * 4 + i];
        float* o = g_attn + ((size_t)(b * SS + srow)) * EE + h * 64 + tx * 4;
#pragma unroll
        for (int j = 0; j < 4; j++) o[j] = acc[i][j] * inv;
    }
}

// ---------------------------------------------------------------------------
// Output projection: g_attn[4096,1024] @ Wo + bo -> d_out
// ---------------------------------------------------------------------------
__global__ void __launch_bounds__(256)
proj_kernel(const float* __restrict__ Wo, const float* __restrict__ bo,
            float* __restrict__ out)
{
    float acc[8][8];
#pragma unroll
    for (int i = 0; i < 8; i++)
#pragma unroll
        for (int j = 0; j < 8; j++) acc[i][j] = 0.f;

    gemm_tile_core(g_attn, Wo, acc);

    const int tid = threadIdx.x;
    const int tx = tid & 15, ty = tid >> 4;
    const int e0 = blockIdx.x * 128 + tx * 8;

#pragma unroll
    for (int i = 0; i < 8; i++) {
        int t = blockIdx.y * 128 + ty * 8 + i;
        float* o = out + (size_t)t * EE + e0;
#pragma unroll
        for (int j = 0; j < 8; j++)
            o[j] = acc[i][j] + bo[e0 + j];
    }
}

// ---------------------------------------------------------------------------
// Launch
// ---------------------------------------------------------------------------
extern "C" void kernel_launch(void* const* d_in, const int* in_sizes, int n_in,
                              void* d_out, int out_size)
{
    const float* x  = (const float*)d_in[0];
    const float* Wq = (const float*)d_in[1];
    const float* bq = (const float*)d_in[2];
    const float* Wk = (const float*)d_in[3];
    const float* bk = (const float*)d_in[4];
    const float* Wv = (const float*)d_in[5];
    const float* bv = (const float*)d_in[6];
    const float* Wo = (const float*)d_in[7];
    const float* bo = (const float*)d_in[8];
    float* out = (float*)d_out;

    // QKV projections: C tiles 128x128 over [4096, 1024], z = {q,k,v}
    dim3 gq(EE / 128, NTOK / 128, 3);
    qkv_kernel<<<gq, 256>>>(x, Wq, bq, Wk, bk, Wv, bv);

    // Flash attention
    const int attn_smem = ATTN_SMEM_FLOATS * (int)sizeof(float);
    (void)cudaFuncSetAttribute(attn_kernel,
                               cudaFuncAttributeMaxDynamicSharedMemorySize,
                               attn_smem);
    dim3 ga(SS / 64, BB * HH);
    attn_kernel<<<ga, 256, attn_smem>>>();

    // Output projection
    dim3 gp(EE / 128, NTOK / 128);
    proj_kernel<<<gp, 256>>>(Wo, bo, out);
}